// round 1
// baseline (speedup 1.0000x reference)
#include <cuda_runtime.h>

#define VDIM 128
#define NB   8
#define SLAB (VDIM * VDIM)            // 16384
#define VOL  (VDIM * VDIM * VDIM)     // 2097152
#define PAD  129                      // smem row stride (float2) to dodge bank conflicts

// Scratch spectrum: 8 * 128^3 complex = 134 MB, static device allocation (allowed).
__device__ float2 g_Z[(size_t)NB * VOL];

// bit-reverse 7 bits
__device__ __forceinline__ int brev7(int x) { return (int)(__brev((unsigned)x) >> 25); }
// storage-index of the negated frequency, in bit-reversed index space
__device__ __forceinline__ int bneg7(int j) {
    int k = brev7(j);
    k = (VDIM - k) & (VDIM - 1);
    return brev7(k);
}

// Batched radix-2 FFT over `nlines` lines of 128 points living in shared memory.
// line l element i at: s[l*lineStride + i*elemStride].
// forward = DIF (natural in -> bit-reversed out), inverse = DIT (bit-rev in -> natural out, unnormalized).
// tw[t] = exp(-2*pi*i * t / 128), t in [0,64).
__device__ __forceinline__ void fft_lines(float2* s, int lineStride, int elemStride,
                                          int nlines, const float2* tw, bool inv) {
    const int tid = threadIdx.x, nt = blockDim.x;
    const int total = nlines * 64;
    if (!inv) {
        #pragma unroll 1
        for (int lh = 6; lh >= 0; --lh) {
            const int half = 1 << lh;
            for (int idx = tid; idx < total; idx += nt) {
                const int line = idx >> 6, bf = idx & 63;
                const int j = bf & (half - 1);
                const int i = ((bf >> lh) << (lh + 1)) + j;
                float2* p = s + line * lineStride;
                float2 a = p[i * elemStride];
                float2 b = p[(i + half) * elemStride];
                float2 w = tw[j << (6 - lh)];
                float2 d = make_float2(a.x - b.x, a.y - b.y);
                p[i * elemStride] = make_float2(a.x + b.x, a.y + b.y);
                p[(i + half) * elemStride] =
                    make_float2(d.x * w.x - d.y * w.y, d.x * w.y + d.y * w.x);
            }
            __syncthreads();
        }
    } else {
        #pragma unroll 1
        for (int lh = 0; lh <= 6; ++lh) {
            const int half = 1 << lh;
            for (int idx = tid; idx < total; idx += nt) {
                const int line = idx >> 6, bf = idx & 63;
                const int j = bf & (half - 1);
                const int i = ((bf >> lh) << (lh + 1)) + j;
                float2* p = s + line * lineStride;
                float2 a = p[i * elemStride];
                float2 b = p[(i + half) * elemStride];
                float2 w = tw[j << (6 - lh)];           // use conj(w) for inverse
                float2 t = make_float2(b.x * w.x + b.y * w.y,
                                       b.y * w.x - b.x * w.y);
                p[i * elemStride] = make_float2(a.x + t.x, a.y + t.y);
                p[(i + half) * elemStride] = make_float2(a.x - t.x, a.y - t.y);
            }
            __syncthreads();
        }
    }
}

__device__ __forceinline__ void init_tw(float2* tw) {
    for (int t = threadIdx.x; t < 64; t += blockDim.x) {
        float sn, cs;
        sincospif(t * (1.0f / 64.0f), &sn, &cs);
        tw[t] = make_float2(cs, -sn);
    }
}

// Pass A: pack z = v1 + i*v2, forward FFT along x then y, per (b,z) slab.
__global__ __launch_bounds__(512) void passA_fwd_xy(const float* __restrict__ v1,
                                                    const float* __restrict__ v2) {
    extern __shared__ float2 sm[];
    float2* tile = sm;                   // [128][PAD]
    float2* tw = sm + VDIM * PAD;        // [64]
    init_tw(tw);
    const size_t base = (size_t)blockIdx.x * SLAB;
    for (int i = threadIdx.x; i < SLAB; i += blockDim.x) {
        const int y = i >> 7, x = i & 127;
        tile[y * PAD + x] = make_float2(v1[base + i], v2[base + i]);
    }
    __syncthreads();
    fft_lines(tile, PAD, 1, VDIM, tw, false);   // along x (rows)
    fft_lines(tile, 1, PAD, VDIM, tw, false);   // along y (columns)
    for (int i = threadIdx.x; i < SLAB; i += blockDim.x) {
        const int y = i >> 7, x = i & 127;
        g_Z[base + i] = tile[y * PAD + x];
    }
}

// H(k) = F1(k) * conj(F2(k)) from packed spectrum: Z = Z(k), Zn = Z(-k).
__device__ __forceinline__ float2 Hval(float2 Z, float2 Zn) {
    const float px = Z.x + Zn.x, py = Z.y - Zn.y;   // P = Z + conj(Zn) = 2*F1
    const float qx = Z.x - Zn.x, qy = Z.y + Zn.y;   // Q = Z - conj(Zn) = 2i*F2
    return make_float2(0.25f * (px * qy - py * qx),
                       0.25f * (px * qx + py * qy));
}

// Pass B: forward z-FFT + pointwise H (Hermitian pairing in smem) + inverse z-FFT, fused.
// Tile pairing: x-tiles of 32 bit-rev indices map under k -> -k as {0->0, 1->1, 2<->3};
// y-slabs pair as jy <-> bneg7(jy). Each CTA holds both halves of every pair.
__global__ __launch_bounds__(256) void passB_z_point() {
    extern __shared__ float2 sm[];       // [64][PAD] : lines 0..31 tileA, 32..63 tileB
    float2* tw = sm + 64 * PAD;
    const int xt = blockIdx.x, jy = blockIdx.y, b = blockIdx.z;
    const int jy2 = bneg7(jy);
    const int xt2 = (xt < 2) ? xt : (5 - xt);
    if (jy2 < jy || (jy2 == jy && xt2 < xt)) return;   // process each pair once
    init_tw(tw);
    const int x0 = xt << 5;
    const size_t vb = (size_t)b * VOL;
    // load: tileA col xi = storage x0+xi @ jy ; tileB col xi = storage bneg7(x0+xi) @ jy2
    for (int i = threadIdx.x; i < VDIM * 32; i += blockDim.x) {
        const int z = i >> 5, xi = i & 31;
        const int xA = x0 + xi;
        const int xB = bneg7(xA);
        const size_t row = vb + (size_t)z * SLAB;
        sm[xi * PAD + z]        = g_Z[row + jy * VDIM + xA];
        sm[(32 + xi) * PAD + z] = g_Z[row + jy2 * VDIM + xB];
    }
    __syncthreads();
    fft_lines(sm, PAD, 1, 64, tw, false);       // forward along z (64 lines)
    // pointwise: each thread owns a (jz, bneg7(jz)) row pair -> in-place safe, no extra sync
    for (int i = threadIdx.x; i < VDIM * 32; i += blockDim.x) {
        const int jz = i >> 5, xi = i & 31;
        const int jz2 = bneg7(jz);
        if (jz2 < jz) continue;
        const float2 a1 = sm[xi * PAD + jz];
        const float2 a2 = sm[xi * PAD + jz2];
        const float2 b1 = sm[(32 + xi) * PAD + jz];
        const float2 b2 = sm[(32 + xi) * PAD + jz2];
        sm[xi * PAD + jz]         = Hval(a1, b2);
        sm[(32 + xi) * PAD + jz]  = Hval(b1, a2);
        sm[xi * PAD + jz2]        = Hval(a2, b1);
        sm[(32 + xi) * PAD + jz2] = Hval(b2, a1);
    }
    __syncthreads();
    fft_lines(sm, PAD, 1, 64, tw, true);        // inverse along z
    for (int i = threadIdx.x; i < VDIM * 32; i += blockDim.x) {
        const int z = i >> 5, xi = i & 31;
        const int xA = x0 + xi;
        const int xB = bneg7(xA);
        const size_t row = vb + (size_t)z * SLAB;
        g_Z[row + jy * VDIM + xA]  = sm[xi * PAD + z];
        g_Z[row + jy2 * VDIM + xB] = sm[(32 + xi) * PAD + z];
    }
}

// Pass C: inverse FFT along y then x per slab, write real part * 1/N^3.
__global__ __launch_bounds__(512) void passC_inv_xy(float* __restrict__ out) {
    extern __shared__ float2 sm[];
    float2* tile = sm;
    float2* tw = sm + VDIM * PAD;
    init_tw(tw);
    const size_t base = (size_t)blockIdx.x * SLAB;
    for (int i = threadIdx.x; i < SLAB; i += blockDim.x) {
        const int y = i >> 7, x = i & 127;
        tile[y * PAD + x] = g_Z[base + i];
    }
    __syncthreads();
    fft_lines(tile, 1, PAD, VDIM, tw, true);    // along y
    fft_lines(tile, PAD, 1, VDIM, tw, true);    // along x
    const float sc = 1.0f / (float)VOL;
    for (int i = threadIdx.x; i < SLAB; i += blockDim.x) {
        const int y = i >> 7, x = i & 127;
        out[base + i] = tile[y * PAD + x].x * sc;
    }
}

extern "C" void kernel_launch(void* const* d_in, const int* in_sizes, int n_in,
                              void* d_out, int out_size) {
    const float* v1 = (const float*)d_in[0];
    const float* v2 = (const float*)d_in[1];
    float* out = (float*)d_out;
    const int smAC = (VDIM * PAD + 64) * (int)sizeof(float2);   // 132,608 B
    const int smB  = (64 * PAD + 64) * (int)sizeof(float2);     //  66,560 B
    cudaFuncSetAttribute(passA_fwd_xy, cudaFuncAttributeMaxDynamicSharedMemorySize, smAC);
    cudaFuncSetAttribute(passC_inv_xy, cudaFuncAttributeMaxDynamicSharedMemorySize, smAC);
    cudaFuncSetAttribute(passB_z_point, cudaFuncAttributeMaxDynamicSharedMemorySize, smB);
    passA_fwd_xy<<<NB * VDIM, 512, smAC>>>(v1, v2);
    passB_z_point<<<dim3(4, VDIM, NB), 256, smB>>>();
    passC_inv_xy<<<NB * VDIM, 512, smAC>>>(out);
}

// round 2
// speedup vs baseline: 2.5936x; 2.5936x over previous
#include <cuda_runtime.h>

#define VDIM 128
#define NB   8
#define SLAB 16384
#define VOL  2097152
#define PAD  129

// Scratch spectrum: 8 * 128^3 complex = 134 MB (static device alloc allowed).
__device__ float2 g_Z[(size_t)NB * VOL];

__device__ __forceinline__ int brev7(int x) { return (int)(__brev((unsigned)x) >> 25); }
__device__ __forceinline__ int bneg7(int j) {
    int k = brev7(j); k = (VDIM - k) & (VDIM - 1); return brev7(k);
}
// bank-swizzled smem index (tile rows y, cols x); avoids 8-way conflicts for
// both stride-8 (pattern A) and stride-16 (pattern B) accesses in both dims.
__device__ __forceinline__ int sidx(int y, int x) {
    return y * PAD + (x ^ ((x >> 3) & 15) ^ ((y >> 3) & 15));
}

__device__ __forceinline__ float2 cmul(float2 a, float2 w) {
    return make_float2(a.x * w.x - a.y * w.y, a.x * w.y + a.y * w.x);
}
__device__ __forceinline__ float2 cmulc(float2 a, float2 w) {  // a * conj(w)
    return make_float2(a.x * w.x + a.y * w.y, a.y * w.x - a.x * w.y);
}
__device__ __forceinline__ void bf_fwd(float2& ra, float2& rb, float2 w) {
    float2 a = ra, b = rb;
    ra = make_float2(a.x + b.x, a.y + b.y);
    rb = cmul(make_float2(a.x - b.x, a.y - b.y), w);
}
__device__ __forceinline__ void bf_inv(float2& ra, float2& rb, float2 w) {
    float2 a = ra, t = cmulc(rb, w);
    ra = make_float2(a.x + t.x, a.y + t.y);
    rb = make_float2(a.x - t.x, a.y - t.y);
}

// Pattern A: r[j] = x[t + 8j].  Forward DIF stages half = 64,32,16,8.
__device__ __forceinline__ void fftA_fwd(float2 r[16], int t, const float2* tw,
                                         const float2* tw4, const float2* tw8) {
    #pragma unroll
    for (int j = 0; j < 8; ++j) bf_fwd(r[j], r[j + 8], tw[t + 8 * j]);
    #pragma unroll
    for (int g = 0; g < 8; ++g) { int j = ((g & ~3) << 1) | (g & 3); bf_fwd(r[j], r[j + 4], tw[2 * (t + 8 * (j & 3))]); }
    #pragma unroll
    for (int g = 0; g < 8; ++g) { int j = ((g & ~1) << 1) | (g & 1); bf_fwd(r[j], r[j + 2], tw4[t + 8 * (j & 1)]); }
    #pragma unroll
    for (int g = 0; g < 8; ++g) { int j = 2 * g; bf_fwd(r[j], r[j + 1], tw8[t]); }
}
__device__ __forceinline__ void fftA_inv(float2 r[16], int t, const float2* tw,
                                         const float2* tw4, const float2* tw8) {
    #pragma unroll
    for (int g = 0; g < 8; ++g) { int j = 2 * g; bf_inv(r[j], r[j + 1], tw8[t]); }
    #pragma unroll
    for (int g = 0; g < 8; ++g) { int j = ((g & ~1) << 1) | (g & 1); bf_inv(r[j], r[j + 2], tw4[t + 8 * (j & 1)]); }
    #pragma unroll
    for (int g = 0; g < 8; ++g) { int j = ((g & ~3) << 1) | (g & 3); bf_inv(r[j], r[j + 4], tw[2 * (t + 8 * (j & 3))]); }
    #pragma unroll
    for (int j = 0; j < 8; ++j) bf_inv(r[j], r[j + 8], tw[t + 8 * j]);
}
// Pattern B: r[m] = x[16u + m].  Forward DIF stages half = 4,2,1.
__device__ __forceinline__ void fftB_fwd(float2 r[16], const float2* tw) {
    #pragma unroll
    for (int g = 0; g < 8; ++g) { int m = ((g & ~3) << 1) | (g & 3); bf_fwd(r[m], r[m + 4], tw[(m & 3) << 4]); }
    #pragma unroll
    for (int g = 0; g < 8; ++g) { int m = ((g & ~1) << 1) | (g & 1); bf_fwd(r[m], r[m + 2], tw[(m & 1) << 5]); }
    #pragma unroll
    for (int g = 0; g < 8; ++g) {
        int m = 2 * g; float2 a = r[m], b = r[m + 1];
        r[m] = make_float2(a.x + b.x, a.y + b.y);
        r[m + 1] = make_float2(a.x - b.x, a.y - b.y);
    }
}
__device__ __forceinline__ void fftB_inv(float2 r[16], const float2* tw) {
    #pragma unroll
    for (int g = 0; g < 8; ++g) {
        int m = 2 * g; float2 a = r[m], b = r[m + 1];
        r[m] = make_float2(a.x + b.x, a.y + b.y);
        r[m + 1] = make_float2(a.x - b.x, a.y - b.y);
    }
    #pragma unroll
    for (int g = 0; g < 8; ++g) { int m = ((g & ~1) << 1) | (g & 1); bf_inv(r[m], r[m + 2], tw[(m & 1) << 5]); }
    #pragma unroll
    for (int g = 0; g < 8; ++g) { int m = ((g & ~3) << 1) | (g & 3); bf_inv(r[m], r[m + 4], tw[(m & 3) << 4]); }
}

__device__ __forceinline__ void init_tw(float2* tw, float2* tw4, float2* tw8) {
    for (int i = threadIdx.x; i < 64; i += blockDim.x) {
        float sn, cs; sincospif(i * (1.0f / 64.0f), &sn, &cs);
        float2 w = make_float2(cs, -sn);
        tw[i] = w;
        if (!(i & 3)) tw4[i >> 2] = w;
        if (!(i & 7)) tw8[i >> 3] = w;
    }
}

// Pass A: pack v1 + i*v2, forward FFT along x then y per (b,z) slab.
__global__ __launch_bounds__(512) void passA(const float* __restrict__ v1,
                                             const float* __restrict__ v2) {
    extern __shared__ float2 sm[];
    float2* tile = sm;
    float2* tw = sm + 128 * PAD; float2* tw4 = tw + 64; float2* tw8 = tw4 + 16;
    init_tw(tw, tw4, tw8);
    const int t = threadIdx.x & 7, slot = threadIdx.x >> 3;
    const size_t base = (size_t)blockIdx.x * SLAB;
    float2 r[16];
    __syncthreads();
    #pragma unroll 1
    for (int rep = 0; rep < 2; ++rep) {            // x-dim: pattern A
        const int y = slot + 64 * rep;
        const float* p1 = v1 + base + y * VDIM;
        const float* p2 = v2 + base + y * VDIM;
        #pragma unroll
        for (int j = 0; j < 16; ++j) r[j] = make_float2(p1[t + 8 * j], p2[t + 8 * j]);
        fftA_fwd(r, t, tw, tw4, tw8);
        #pragma unroll
        for (int j = 0; j < 16; ++j) tile[sidx(y, t + 8 * j)] = r[j];
    }
    __syncwarp();
    #pragma unroll 1
    for (int rep = 0; rep < 2; ++rep) {            // x-dim: pattern B
        const int y = slot + 64 * rep;
        #pragma unroll
        for (int m = 0; m < 16; ++m) r[m] = tile[sidx(y, 16 * t + m)];
        fftB_fwd(r, tw);
        #pragma unroll
        for (int m = 0; m < 16; ++m) tile[sidx(y, 16 * t + m)] = r[m];
    }
    __syncthreads();
    #pragma unroll 1
    for (int rep = 0; rep < 2; ++rep) {            // y-dim: pattern A
        const int x = slot + 64 * rep;
        #pragma unroll
        for (int j = 0; j < 16; ++j) r[j] = tile[sidx(t + 8 * j, x)];
        fftA_fwd(r, t, tw, tw4, tw8);
        #pragma unroll
        for (int j = 0; j < 16; ++j) tile[sidx(t + 8 * j, x)] = r[j];
    }
    __syncwarp();
    #pragma unroll 1
    for (int rep = 0; rep < 2; ++rep) {            // y-dim: pattern B -> gmem
        const int x = slot + 64 * rep;
        #pragma unroll
        for (int m = 0; m < 16; ++m) r[m] = tile[sidx(16 * t + m, x)];
        fftB_fwd(r, tw);
        #pragma unroll
        for (int m = 0; m < 16; ++m) g_Z[base + (size_t)(16 * t + m) * VDIM + x] = r[m];
    }
}

__device__ __forceinline__ float2 Hval(float2 Z, float2 Zn) {
    const float px = Z.x + Zn.x, py = Z.y - Zn.y;   // 2*F1
    const float qx = Z.x - Zn.x, qy = Z.y + Zn.y;   // 2i*F2
    return make_float2(0.25f * (px * qy - py * qx),
                       0.25f * (px * qx + py * qy));
}

// Pass B: forward z-FFT + pointwise H (Hermitian pairing) + inverse z-FFT, fused.
// Each CTA owns x-tile xt @ row jy AND partner tile xt2 @ row jy2=bneg7(jy); the
// bneg7-image of a contiguous 32-tile is the contiguous tile xt2, so the partner
// is loaded coalesced in its own storage order and paired via a per-column lookup.
__global__ __launch_bounds__(512) void passB() {
    extern __shared__ float2 sm[];
    float2* tile = sm;                              // 64 lines x 128
    float2* tw = sm + 64 * PAD; float2* tw4 = tw + 64; float2* tw8 = tw4 + 16;
    const int xt = blockIdx.x, jy = blockIdx.y, b = blockIdx.z;
    const int jy2 = bneg7(jy);
    const int xt2 = (xt < 2) ? xt : (5 - xt);
    if (jy2 < jy || (jy2 == jy && xt2 < xt)) return;
    init_tw(tw, tw4, tw8);
    const int t = threadIdx.x & 7, l = threadIdx.x >> 3;    // l = 0..63
    const int xi = l & 31;
    const int gx = (l < 32) ? (32 * xt + xi) : (32 * xt2 + xi);
    const int gy = (l < 32) ? jy : jy2;
    const size_t gb = (size_t)b * VOL + (size_t)gy * VDIM + gx;
    float2 r[16];
    __syncthreads();
    #pragma unroll
    for (int j = 0; j < 16; ++j) r[j] = g_Z[gb + (size_t)(t + 8 * j) * SLAB];
    fftA_fwd(r, t, tw, tw4, tw8);
    #pragma unroll
    for (int j = 0; j < 16; ++j) tile[sidx(l, t + 8 * j)] = r[j];
    __syncwarp();
    #pragma unroll
    for (int m = 0; m < 16; ++m) r[m] = tile[sidx(l, 16 * t + m)];
    fftB_fwd(r, tw);
    #pragma unroll
    for (int m = 0; m < 16; ++m) tile[sidx(l, 16 * t + m)] = r[m];
    __syncthreads();
    // pointwise, each thread owns a (jz, bneg7(jz)) x (colA, colB) quad
    for (int i = threadIdx.x; i < VDIM * 32; i += blockDim.x) {
        const int jz = i >> 5, xiA = i & 31;
        const int jz2 = bneg7(jz);
        if (jz2 < jz) continue;
        const int lb = 32 + (bneg7(32 * xt + xiA) - 32 * xt2);
        const float2 a1 = tile[sidx(xiA, jz)], a2 = tile[sidx(xiA, jz2)];
        const float2 b1 = tile[sidx(lb, jz)],  b2 = tile[sidx(lb, jz2)];
        tile[sidx(xiA, jz)]  = Hval(a1, b2);
        tile[sidx(lb,  jz)]  = Hval(b1, a2);
        tile[sidx(xiA, jz2)] = Hval(a2, b1);
        tile[sidx(lb,  jz2)] = Hval(b2, a1);
    }
    __syncthreads();
    #pragma unroll
    for (int m = 0; m < 16; ++m) r[m] = tile[sidx(l, 16 * t + m)];
    fftB_inv(r, tw);
    #pragma unroll
    for (int m = 0; m < 16; ++m) tile[sidx(l, 16 * t + m)] = r[m];
    __syncwarp();
    #pragma unroll
    for (int j = 0; j < 16; ++j) r[j] = tile[sidx(l, t + 8 * j)];
    fftA_inv(r, t, tw, tw4, tw8);
    #pragma unroll
    for (int j = 0; j < 16; ++j) g_Z[gb + (size_t)(t + 8 * j) * SLAB] = r[j];
}

// Pass C: inverse FFT along y then x per slab, write real part / N^3.
__global__ __launch_bounds__(512) void passC(float* __restrict__ out) {
    extern __shared__ float2 sm[];
    float2* tile = sm;
    float2* tw = sm + 128 * PAD; float2* tw4 = tw + 64; float2* tw8 = tw4 + 16;
    init_tw(tw, tw4, tw8);
    const int t = threadIdx.x & 7, slot = threadIdx.x >> 3;
    const size_t base = (size_t)blockIdx.x * SLAB;
    const float sc = 1.0f / (float)VOL;
    float2 r[16];
    __syncthreads();
    #pragma unroll 1
    for (int rep = 0; rep < 2; ++rep) {            // y-dim: pattern B from gmem
        const int x = slot + 64 * rep;
        #pragma unroll
        for (int m = 0; m < 16; ++m) r[m] = g_Z[base + (size_t)(16 * t + m) * VDIM + x];
        fftB_inv(r, tw);
        #pragma unroll
        for (int m = 0; m < 16; ++m) tile[sidx(16 * t + m, x)] = r[m];
    }
    __syncwarp();
    #pragma unroll 1
    for (int rep = 0; rep < 2; ++rep) {            // y-dim: pattern A
        const int x = slot + 64 * rep;
        #pragma unroll
        for (int j = 0; j < 16; ++j) r[j] = tile[sidx(t + 8 * j, x)];
        fftA_inv(r, t, tw, tw4, tw8);
        #pragma unroll
        for (int j = 0; j < 16; ++j) tile[sidx(t + 8 * j, x)] = r[j];
    }
    __syncthreads();
    #pragma unroll 1
    for (int rep = 0; rep < 2; ++rep) {            // x-dim: pattern B
        const int y = slot + 64 * rep;
        #pragma unroll
        for (int m = 0; m < 16; ++m) r[m] = tile[sidx(y, 16 * t + m)];
        fftB_inv(r, tw);
        #pragma unroll
        for (int m = 0; m < 16; ++m) tile[sidx(y, 16 * t + m)] = r[m];
    }
    __syncwarp();
    #pragma unroll 1
    for (int rep = 0; rep < 2; ++rep) {            // x-dim: pattern A -> out
        const int y = slot + 64 * rep;
        #pragma unroll
        for (int j = 0; j < 16; ++j) r[j] = tile[sidx(y, t + 8 * j)];
        fftA_inv(r, t, tw, tw4, tw8);
        #pragma unroll
        for (int j = 0; j < 16; ++j) out[base + y * VDIM + t + 8 * j] = r[j].x * sc;
    }
}

extern "C" void kernel_launch(void* const* d_in, const int* in_sizes, int n_in,
                              void* d_out, int out_size) {
    const float* v1 = (const float*)d_in[0];
    const float* v2 = (const float*)d_in[1];
    float* out = (float*)d_out;
    const int smAC = (128 * PAD + 64 + 16 + 8) * (int)sizeof(float2);   // ~132.8 KB
    const int smB  = (64 * PAD + 64 + 16 + 8) * (int)sizeof(float2);    // ~66.8 KB
    cudaFuncSetAttribute(passA, cudaFuncAttributeMaxDynamicSharedMemorySize, smAC);
    cudaFuncSetAttribute(passC, cudaFuncAttributeMaxDynamicSharedMemorySize, smAC);
    cudaFuncSetAttribute(passB, cudaFuncAttributeMaxDynamicSharedMemorySize, smB);
    passA<<<NB * VDIM, 512, smAC>>>(v1, v2);
    passB<<<dim3(4, VDIM, NB), 512, smB>>>();
    passC<<<NB * VDIM, 512, smAC>>>(out);
}